// round 1
// baseline (speedup 1.0000x reference)
#include <cuda_runtime.h>
#include <cstddef>

#define NF 1025      // n_stft
#define NM 128       // n_mels
#define NB 4         // batch
#define TT 1024      // time
#define ROWS 8       // rows (b,t) per CTA
#define NTHREADS 256
#define ITERS 20
#define NBLOCKS ((NB * TT) / ROWS)   // 512
#define DIFF_STRIDE 132              // NM + pad (mi=127 reads diff[128])

__device__ float g_w0[NF];
__device__ float g_w1[NF];
__device__ unsigned char g_mi[NF];
__device__ int g_fs[NM];
__device__ int g_fe[NM];

// ---------------------------------------------------------------------------
// Prep: extract sparse structure of fb (each freq has <=2 adjacent nonzero
// mels; each mel's support is a contiguous freq range).
// ---------------------------------------------------------------------------
__global__ void prep_reset() {
    int m = threadIdx.x;
    if (m < NM) { g_fs[m] = NF; g_fe[m] = 0; }
}

__global__ void prep_build(const float* __restrict__ fb) {
    int f = blockIdx.x * blockDim.x + threadIdx.x;
    if (f >= NF) return;
    const float* row = fb + (size_t)f * NM;
    int mi = -1;
    for (int m = 0; m < NM; m++) {
        if (row[m] > 0.0f) { mi = m; break; }
    }
    float w0 = 0.0f, w1 = 0.0f;
    if (mi >= 0) {
        w0 = row[mi];
        w1 = (mi + 1 < NM) ? row[mi + 1] : 0.0f;
    } else {
        mi = 0;
    }
    g_mi[f] = (unsigned char)mi;
    g_w0[f] = w0;
    g_w1[f] = w1;
    if (w0 > 0.0f) { atomicMin(&g_fs[mi], f); atomicMax(&g_fe[mi], f + 1); }
    if (w1 > 0.0f) { atomicMin(&g_fs[mi + 1], f); atomicMax(&g_fe[mi + 1], f + 1); }
}

// ---------------------------------------------------------------------------
// Main: each CTA runs the full 20-iteration SGD for 8 independent (b,t) rows.
// ---------------------------------------------------------------------------
__global__ __launch_bounds__(NTHREADS, 2)
void invmel_main(const float* __restrict__ melspec,
                 const float* __restrict__ spec_init,
                 float* __restrict__ out) {
    extern __shared__ float sm[];
    float* s_spec = sm;                           // ROWS*NF
    float* s_diff = s_spec + ROWS * NF;           // ROWS*DIFF_STRIDE
    float* s_mel  = s_diff + ROWS * DIFF_STRIDE;  // ROWS*NM
    float* s_part = s_mel  + ROWS * NM;           // ROWS*NM   (B-half partials)
    float* s_w    = s_part + ROWS * NM;           // 2*NF      (w0,w1 interleaved)
    int*   s_fs   = (int*)(s_w + 2 * NF);         // NM
    int*   s_fe   = s_fs + NM;                    // NM
    unsigned char* s_mi = (unsigned char*)(s_fe + NM); // NF

    const float c_LR  = 0.3f;
    const float c_MOM = 0.9f;
    const float c_INV = 2.0f / (float)(NB * TT);

    const int tid  = threadIdx.x;
    const int row0 = blockIdx.x * ROWS;
    const int b    = row0 / TT;
    const int t0   = row0 % TT;

    // --- stage sparse fb + inputs into shared ---
    for (int f = tid; f < NF; f += NTHREADS) {
        s_w[2 * f]     = g_w0[f];
        s_w[2 * f + 1] = g_w1[f];
        s_mi[f]        = g_mi[f];
    }
    if (tid < NM) { s_fs[tid] = g_fs[tid]; s_fe[tid] = g_fe[tid]; }
    for (int i = tid; i < ROWS * DIFF_STRIDE; i += NTHREADS) s_diff[i] = 0.0f;
    for (int i = tid; i < ROWS * NM; i += NTHREADS) {
        int r = i >> 7;
        int m = i & (NM - 1);
        s_mel[i] = melspec[((size_t)b * NM + m) * TT + (t0 + r)];
    }
    for (int r = 0; r < ROWS; r++) {
        for (int f = tid; f < NF; f += NTHREADS) {
            s_spec[r * NF + f] = spec_init[(size_t)(row0 + r) * NF + f];
        }
    }
    __syncthreads();

    // --- gather task setup (load-balanced: pair mel m with mel 127-m) ---
    const int mA = tid & (NM - 1);
    const int rg = (tid >> 7) & 1;    // row group: rows [rg*4, rg*4+4)
    const int mB = (NM - 1) - mA;
    const int r0 = rg * 4;

    int fsA = s_fs[mA], feA = s_fe[mA];
    if (feA < fsA) feA = fsA;
    const int midA = fsA + ((feA - fsA + 1) >> 1);
    int fsB = s_fs[mB], feB = s_fe[mB];
    if (feB < fsB) feB = fsB;
    const int midB = fsB + ((feB - fsB + 1) >> 1);

    const float melv0 = s_mel[(r0 + 0) * NM + mA];
    const float melv1 = s_mel[(r0 + 1) * NM + mA];
    const float melv2 = s_mel[(r0 + 2) * NM + mA];
    const float melv3 = s_mel[(r0 + 3) * NM + mA];

    // --- update-phase ownership: thread t owns freqs [5t, 5t+5) (205 owners) ---
    const int f0 = tid * 5;
    const bool owner = (f0 < NF);   // 205*5 = 1025 exactly
    float w0r[5], w1r[5];
    int   mir[5];
    float rb[5][ROWS];              // momentum buffers, register-resident
    if (owner) {
#pragma unroll
        for (int k = 0; k < 5; k++) {
            int f = f0 + k;
            w0r[k] = s_w[2 * f];
            w1r[k] = s_w[2 * f + 1];
            mir[k] = s_mi[f];
#pragma unroll
            for (int r = 0; r < ROWS; r++) rb[k][r] = 0.0f;
        }
    }

    for (int it = 0; it < ITERS; it++) {
        // ---- phase 1: mel_est gather (A: first half of mA, B: second half of mB)
        float a0 = 0.f, a1 = 0.f, a2 = 0.f, a3 = 0.f;
#pragma unroll 4
        for (int f = fsA; f < midA; f++) {
            float w = s_w[2 * f + (s_mi[f] != mA)];
            a0 = fmaf(w, s_spec[(r0 + 0) * NF + f], a0);
            a1 = fmaf(w, s_spec[(r0 + 1) * NF + f], a1);
            a2 = fmaf(w, s_spec[(r0 + 2) * NF + f], a2);
            a3 = fmaf(w, s_spec[(r0 + 3) * NF + f], a3);
        }
        float p0 = 0.f, p1 = 0.f, p2 = 0.f, p3 = 0.f;
#pragma unroll 4
        for (int f = midB; f < feB; f++) {
            float w = s_w[2 * f + (s_mi[f] != mB)];
            p0 = fmaf(w, s_spec[(r0 + 0) * NF + f], p0);
            p1 = fmaf(w, s_spec[(r0 + 1) * NF + f], p1);
            p2 = fmaf(w, s_spec[(r0 + 2) * NF + f], p2);
            p3 = fmaf(w, s_spec[(r0 + 3) * NF + f], p3);
        }
        s_part[(r0 + 0) * NM + mB] = p0;
        s_part[(r0 + 1) * NM + mB] = p1;
        s_part[(r0 + 2) * NM + mB] = p2;
        s_part[(r0 + 3) * NM + mB] = p3;
        __syncthreads();

        // ---- phase 2: diff = mel - est
        s_diff[(r0 + 0) * DIFF_STRIDE + mA] = melv0 - a0 - s_part[(r0 + 0) * NM + mA];
        s_diff[(r0 + 1) * DIFF_STRIDE + mA] = melv1 - a1 - s_part[(r0 + 1) * NM + mA];
        s_diff[(r0 + 2) * DIFF_STRIDE + mA] = melv2 - a2 - s_part[(r0 + 2) * NM + mA];
        s_diff[(r0 + 3) * DIFF_STRIDE + mA] = melv3 - a3 - s_part[(r0 + 3) * NM + mA];
        __syncthreads();

        // ---- phase 3: grad + momentum + clamp update
        if (owner) {
#pragma unroll
            for (int k = 0; k < 5; k++) {
                const float w0  = w0r[k];
                const float w1  = w1r[k];
                const int   mi0 = mir[k];
                const int   f   = f0 + k;
#pragma unroll
                for (int r = 0; r < ROWS; r++) {
                    float d  = s_diff[r * DIFF_STRIDE + mi0] * w0
                             + s_diff[r * DIFF_STRIDE + mi0 + 1] * w1;
                    float gd = -c_INV * d;
                    float bv = fmaf(c_MOM, rb[k][r], gd);
                    rb[k][r] = bv;
                    float sv = fmaxf(fmaf(-c_LR, bv, s_spec[r * NF + f]), 0.0f);
                    s_spec[r * NF + f] = sv;
                }
            }
        }
        __syncthreads();
    }

    // --- output: out[b][f][t0..t0+7] = spec rows, 2x float4 (32B sectors) ---
    for (int f = tid; f < NF; f += NTHREADS) {
        float4 v0 = make_float4(s_spec[0 * NF + f], s_spec[1 * NF + f],
                                s_spec[2 * NF + f], s_spec[3 * NF + f]);
        float4 v1 = make_float4(s_spec[4 * NF + f], s_spec[5 * NF + f],
                                s_spec[6 * NF + f], s_spec[7 * NF + f]);
        float4* p = reinterpret_cast<float4*>(out + ((size_t)b * NF + f) * TT + t0);
        p[0] = v0;
        p[1] = v1;
    }
}

// ---------------------------------------------------------------------------
extern "C" void kernel_launch(void* const* d_in, const int* in_sizes, int n_in,
                              void* d_out, int out_size) {
    // Identify inputs by element count (robust to metadata ordering):
    // melspec 4*128*1024=524288, spec_init 4*1024*1025=4198400, fb 1025*128=131200
    const float* melspec = nullptr;
    const float* spec_init = nullptr;
    const float* fb = nullptr;
    for (int i = 0; i < n_in; i++) {
        if (in_sizes[i] == NB * NM * TT)      melspec  = (const float*)d_in[i];
        else if (in_sizes[i] == NB * TT * NF) spec_init = (const float*)d_in[i];
        else if (in_sizes[i] == NF * NM)      fb        = (const float*)d_in[i];
    }
    float* out = (float*)d_out;

    const int smem_bytes =
        (ROWS * NF + ROWS * DIFF_STRIDE + ROWS * NM + ROWS * NM + 2 * NF) * 4
        + 2 * NM * 4       // s_fs, s_fe
        + (NF + 3);        // s_mi + pad

    cudaFuncSetAttribute(invmel_main, cudaFuncAttributeMaxDynamicSharedMemorySize,
                         smem_bytes);

    prep_reset<<<1, NM>>>();
    prep_build<<<(NF + 255) / 256, 256>>>(fb);
    invmel_main<<<NBLOCKS, NTHREADS, smem_bytes>>>(melspec, spec_init, out);
}

// round 2
// speedup vs baseline: 1.2047x; 1.2047x over previous
#include <cuda_runtime.h>
#include <cstddef>

#define NF 1025      // n_stft
#define NFP 1028     // padded spec row stride in floats (= 257 float4, odd mod 8 granules)
#define NM 128       // n_mels
#define NB 4         // batch
#define TT 1024      // time
#define ROWS 8       // rows (b,t) per CTA
#define NTHREADS 256
#define ITERS 20
#define NBLOCKS ((NB * TT) / ROWS)   // 512
#define DSTRIDE 129  // diff row stride (mi+1 can reach 128)
#define GMAX 1024    // max total float4 weight groups (bound: <=897)

__device__ float g_w0[NF];
__device__ float g_w1[NF];
__device__ int   g_mi[NF];
__device__ int   g_fs[NM];
__device__ int   g_fe[NM];
__device__ int   g_meta[2 * 2 * NM];   // per task: {a4 | ng<<16, woff}
__device__ float4 g_wd[GMAX];
__device__ int   g_tot;

// ---------------------------------------------------------------------------
// Prep 1: reset per-mel support ranges
// ---------------------------------------------------------------------------
__global__ void prep_reset() {
    int m = threadIdx.x;
    if (m < NM) { g_fs[m] = NF; g_fe[m] = 0; }
}

// ---------------------------------------------------------------------------
// Prep 2: per-freq sparse structure (<=2 adjacent nonzero mels per freq)
// ---------------------------------------------------------------------------
__global__ void prep_build(const float* __restrict__ fb) {
    int f = blockIdx.x * blockDim.x + threadIdx.x;
    if (f >= NF) return;
    const float* row = fb + (size_t)f * NM;
    int mi = -1;
    for (int m = 0; m < NM; m++) {
        if (row[m] > 0.0f) { mi = m; break; }
    }
    float w0 = 0.0f, w1 = 0.0f;
    if (mi >= 0) {
        w0 = row[mi];
        w1 = (mi + 1 < NM) ? row[mi + 1] : 0.0f;
    } else {
        mi = 0;
    }
    g_mi[f] = mi;
    g_w0[f] = w0;
    g_w1[f] = w1;
    if (w0 > 0.0f) { atomicMin(&g_fs[mi], f); atomicMax(&g_fe[mi], f + 1); }
    if (w1 > 0.0f) { atomicMin(&g_fs[mi + 1], f); atomicMax(&g_fe[mi + 1], f + 1); }
}

// ---------------------------------------------------------------------------
// Prep 3: build 256 gather tasks (mel m, half h) with float4-aligned dense
// weight windows (zeros outside the support; exact values read from fb).
// ---------------------------------------------------------------------------
__global__ void prep_tasks(const float* __restrict__ fb) {
    __shared__ int s_ng[2 * NM];
    __shared__ int s_off[2 * NM + 1];
    int t = threadIdx.x;          // t = h*128 + m
    int m = t & (NM - 1);
    int h = t >> 7;

    int fs = g_fs[m], fe = g_fe[m];
    if (fe < fs) fe = fs;
    int mid = fs + ((fe - fs + 1) >> 1);
    int st = h ? mid : fs;
    int en = h ? fe : mid;
    int a4 = st >> 2;
    int e4 = (en + 3) >> 2;
    int ng = (en > st) ? (e4 - a4) : 0;
    if (ng == 0) a4 = 0;
    s_ng[t] = ng;
    __syncthreads();

    if (t == 0) {
        int acc = 0;
        for (int i = 0; i < 2 * NM; i++) { s_off[i] = acc; acc += s_ng[i]; }
        s_off[2 * NM] = acc;
        g_tot = acc;
    }
    __syncthreads();

    int woff = s_off[t];
    g_meta[2 * t]     = a4 | (ng << 16);
    g_meta[2 * t + 1] = woff;

    float* wd = (float*)g_wd;
    for (int j = 0; j < ng * 4; j++) {
        int f = a4 * 4 + j;
        float w = 0.0f;
        if (f >= st && f < en && f < NF) w = fb[(size_t)f * NM + m];
        wd[woff * 4 + j] = w;
    }
}

// ---------------------------------------------------------------------------
// Main: each CTA runs the full 20-iteration SGD for 8 independent (b,t) rows.
// smem = spec(8x1028f) + diff(8x129f) + weights(GMAX float4) = 53408 B -> occ 4
// ---------------------------------------------------------------------------
__global__ __launch_bounds__(NTHREADS, 4)
void invmel_main(const float* __restrict__ melspec,
                 const float* __restrict__ spec_init,
                 float* __restrict__ out) {
    extern __shared__ float sm[];
    float*  s_spec = sm;                          // ROWS * NFP
    float*  s_diff = s_spec + ROWS * NFP;         // ROWS * DSTRIDE
    float4* s_wd4  = (float4*)(s_diff + ROWS * DSTRIDE);

    const float c_LR  = 0.3f;
    const float c_MOM = 0.9f;
    const float c_INV = 2.0f / (float)(NB * TT);

    const int tid  = threadIdx.x;
    const int row0 = blockIdx.x * ROWS;
    const int b    = row0 / TT;
    const int t0   = row0 % TT;
    const int mA   = tid & (NM - 1);
    const int rg   = tid >> 7;
    const int r0   = rg * 4;

    // --- stage weights + spec into shared ---
    const int tot = g_tot;
    for (int i = tid; i < tot; i += NTHREADS) s_wd4[i] = g_wd[i];
    for (int i = tid; i < ROWS * DSTRIDE; i += NTHREADS) s_diff[i] = 0.0f;
    for (int r = 0; r < ROWS; r++) {
        for (int f = tid; f < 1024; f += NTHREADS) {
            s_spec[r * NFP + f] = spec_init[(size_t)(row0 + r) * NF + f];
        }
    }

    // mel targets for this thread's (mel mA, rows r0..r0+3): one LDG.128
    const float4 melv =
        *(const float4*)&melspec[((size_t)b * NM + mA) * TT + t0 + r0];

    // gather tasks: first half of mA, second half of (127 - mA)
    const int ta = mA;
    const int tb = NM + (NM - 1 - mA);
    const int pa0 = g_meta[2 * ta], pa1 = g_meta[2 * ta + 1];
    const int pb0 = g_meta[2 * tb], pb1 = g_meta[2 * tb + 1];
    const int aA = pa0 & 0xFFFF, ngA = pa0 >> 16, woA = pa1;
    const int aB = pb0 & 0xFFFF, ngB = pb0 >> 16, woB = pb1;
    const int mb = NM - 1 - mA;

    // update-phase ownership: f = k*256 + tid, k<4 (f=0 & f=1024 have w==0)
    float w0r[4], w1r[4];
    int   mir[4];
    float rb[4][ROWS];
#pragma unroll
    for (int k = 0; k < 4; k++) {
        int f = k * NTHREADS + tid;
        w0r[k] = g_w0[f];
        w1r[k] = g_w1[f];
        mir[k] = g_mi[f];
#pragma unroll
        for (int r = 0; r < ROWS; r++) rb[k][r] = 0.0f;
    }
    __syncthreads();

    const float4* s_sp4 = (const float4*)s_spec;
    const int rowg0 = (r0 + 0) * (NFP / 4);
    const int rowg1 = (r0 + 1) * (NFP / 4);
    const int rowg2 = (r0 + 2) * (NFP / 4);
    const int rowg3 = (r0 + 3) * (NFP / 4);

    for (int it = 0; it < ITERS; it++) {
        // ---- phase 1: float4 gather over dense weight windows
        float a0 = 0.f, a1 = 0.f, a2 = 0.f, a3 = 0.f;
        for (int g = 0; g < ngA; g++) {
            float4 w  = s_wd4[woA + g];
            float4 x0 = s_sp4[rowg0 + aA + g];
            float4 x1 = s_sp4[rowg1 + aA + g];
            float4 x2 = s_sp4[rowg2 + aA + g];
            float4 x3 = s_sp4[rowg3 + aA + g];
            a0 = fmaf(w.w, x0.w, fmaf(w.z, x0.z, fmaf(w.y, x0.y, fmaf(w.x, x0.x, a0))));
            a1 = fmaf(w.w, x1.w, fmaf(w.z, x1.z, fmaf(w.y, x1.y, fmaf(w.x, x1.x, a1))));
            a2 = fmaf(w.w, x2.w, fmaf(w.z, x2.z, fmaf(w.y, x2.y, fmaf(w.x, x2.x, a2))));
            a3 = fmaf(w.w, x3.w, fmaf(w.z, x3.z, fmaf(w.y, x3.y, fmaf(w.x, x3.x, a3))));
        }
        float p0 = 0.f, p1 = 0.f, p2 = 0.f, p3 = 0.f;
        for (int g = 0; g < ngB; g++) {
            float4 w  = s_wd4[woB + g];
            float4 x0 = s_sp4[rowg0 + aB + g];
            float4 x1 = s_sp4[rowg1 + aB + g];
            float4 x2 = s_sp4[rowg2 + aB + g];
            float4 x3 = s_sp4[rowg3 + aB + g];
            p0 = fmaf(w.w, x0.w, fmaf(w.z, x0.z, fmaf(w.y, x0.y, fmaf(w.x, x0.x, p0))));
            p1 = fmaf(w.w, x1.w, fmaf(w.z, x1.z, fmaf(w.y, x1.y, fmaf(w.x, x1.x, p1))));
            p2 = fmaf(w.w, x2.w, fmaf(w.z, x2.z, fmaf(w.y, x2.y, fmaf(w.x, x2.x, p2))));
            p3 = fmaf(w.w, x3.w, fmaf(w.z, x3.z, fmaf(w.y, x3.y, fmaf(w.x, x3.x, p3))));
        }
        // stash partial (second half of mel mb) in s_diff temporarily
        s_diff[(r0 + 0) * DSTRIDE + mb] = p0;
        s_diff[(r0 + 1) * DSTRIDE + mb] = p1;
        s_diff[(r0 + 2) * DSTRIDE + mb] = p2;
        s_diff[(r0 + 3) * DSTRIDE + mb] = p3;
        __syncthreads();

        // ---- phase 2: diff = mel - est (combine own first half + stashed half)
        float d0 = melv.x - a0 - s_diff[(r0 + 0) * DSTRIDE + mA];
        float d1 = melv.y - a1 - s_diff[(r0 + 1) * DSTRIDE + mA];
        float d2 = melv.z - a2 - s_diff[(r0 + 2) * DSTRIDE + mA];
        float d3 = melv.w - a3 - s_diff[(r0 + 3) * DSTRIDE + mA];
        s_diff[(r0 + 0) * DSTRIDE + mA] = d0;
        s_diff[(r0 + 1) * DSTRIDE + mA] = d1;
        s_diff[(r0 + 2) * DSTRIDE + mA] = d2;
        s_diff[(r0 + 3) * DSTRIDE + mA] = d3;
        __syncthreads();

        // ---- phase 3: grad + momentum + clamp (conflict-free lane stride 1)
#pragma unroll
        for (int k = 0; k < 4; k++) {
            const float w0 = w0r[k];
            const float w1 = w1r[k];
            const int   mi = mir[k];
            const int   f  = k * NTHREADS + tid;
#pragma unroll
            for (int r = 0; r < ROWS; r++) {
                float d  = s_diff[r * DSTRIDE + mi] * w0
                         + s_diff[r * DSTRIDE + mi + 1] * w1;
                float bv = fmaf(c_MOM, rb[k][r], -c_INV * d);
                rb[k][r] = bv;
                float sv = fmaxf(fmaf(-c_LR, bv, s_spec[r * NFP + f]), 0.0f);
                s_spec[r * NFP + f] = sv;
            }
        }
        __syncthreads();
    }

    // --- output: out[b][f][t0..t0+7], two STG.128 per owned f ---
#pragma unroll
    for (int k = 0; k < 4; k++) {
        const int f = k * NTHREADS + tid;
        float4 v0 = make_float4(s_spec[0 * NFP + f], s_spec[1 * NFP + f],
                                s_spec[2 * NFP + f], s_spec[3 * NFP + f]);
        float4 v1 = make_float4(s_spec[4 * NFP + f], s_spec[5 * NFP + f],
                                s_spec[6 * NFP + f], s_spec[7 * NFP + f]);
        float4* p = (float4*)&out[((size_t)b * NF + f) * TT + t0];
        p[0] = v0;
        p[1] = v1;
    }
    // f = 1024: fb row is identically zero -> spec stays at init (>=0)
    if (tid < ROWS) {
        out[((size_t)b * NF + 1024) * TT + t0 + tid] =
            spec_init[(size_t)(row0 + tid) * NF + 1024];
    }
}

// ---------------------------------------------------------------------------
extern "C" void kernel_launch(void* const* d_in, const int* in_sizes, int n_in,
                              void* d_out, int out_size) {
    const float* melspec = nullptr;
    const float* spec_init = nullptr;
    const float* fb = nullptr;
    for (int i = 0; i < n_in; i++) {
        if (in_sizes[i] == NB * NM * TT)      melspec   = (const float*)d_in[i];
        else if (in_sizes[i] == NB * TT * NF) spec_init = (const float*)d_in[i];
        else if (in_sizes[i] == NF * NM)      fb        = (const float*)d_in[i];
    }
    float* out = (float*)d_out;

    const int smem_bytes = (ROWS * NFP + ROWS * DSTRIDE) * 4 + GMAX * 16; // 53408

    cudaFuncSetAttribute(invmel_main, cudaFuncAttributeMaxDynamicSharedMemorySize,
                         smem_bytes);

    prep_reset<<<1, NM>>>();
    prep_build<<<(NF + 255) / 256, 256>>>(fb);
    prep_tasks<<<1, 2 * NM>>>(fb);
    invmel_main<<<NBLOCKS, NTHREADS, smem_bytes>>>(melspec, spec_init, out);
}